// round 5
// baseline (speedup 1.0000x reference)
#include <cuda_runtime.h>
#include <cuda_bf16.h>

#define NN 100000
#define NE 1200000
#define NG 2048
#define DD 64
#define SCAN_B 1024
#define SCAN_NB 98   // 98*1024 = 100352 >= NN

// Scratch (allocation-free, __device__ globals)
__device__ float g_h0[(size_t)NN * DD];
__device__ float g_h1[(size_t)NN * DD];
__device__ float g_h2[(size_t)NN * DD];
__device__ float g_agg[(size_t)NN * DD];      // mean buffer
__device__ float g_pool[(size_t)NG * DD];
__device__ float g_gcnt[NG];
__device__ int   g_deg[NN];
__device__ int   g_off[NN];
__device__ int   g_cursor[NN];
__device__ int   g_elist[NE];
__device__ int   g_bsum[SCAN_NB];
__device__ int   g_bpre[SCAN_NB];

typedef unsigned long long u64;

// ---------- packed fp32 helpers ----------
__device__ __forceinline__ u64 pk2(float lo, float hi) {
    u64 r;
    asm("mov.b64 %0, {%1, %2};" : "=l"(r) : "f"(lo), "f"(hi));
    return r;
}
__device__ __forceinline__ void upk2(float& lo, float& hi, u64 v) {
    asm("mov.b64 {%0, %1}, %2;" : "=f"(lo), "=f"(hi) : "l"(v));
}
__device__ __forceinline__ void ffma2(u64& acc, u64 a, u64 b) {
    asm("fma.rn.f32x2 %0, %1, %2, %0;" : "+l"(acc) : "l"(a), "l"(b));
}
__device__ __forceinline__ void red_v4(float* p, float4 v) {
    asm volatile("red.global.add.v4.f32 [%0], {%1, %2, %3, %4};"
                 :: "l"(p), "f"(v.x), "f"(v.y), "f"(v.z), "f"(v.w) : "memory");
}

// ---------- fused: h0[n] = emb[x[n]]  AND  deg[dst[e]] += 1 ----------
__global__ void k_gatherdeg(const int* __restrict__ x, const float* __restrict__ emb,
                            float* __restrict__ h, const int* __restrict__ dst,
                            int* __restrict__ deg) {
    int t = blockIdx.x * blockDim.x + threadIdx.x;
    if (t < NN * 16) {
        int n = t >> 4, j = t & 15;
        const float4* e = (const float4*)(emb + (size_t)x[n] * DD);
        ((float4*)(h + (size_t)n * DD))[j] = e[j];
    } else {
        int e = t - NN * 16;
        if (e < NE) atomicAdd(&deg[dst[e]], 1);
    }
}

// ---------- CSR build: scans + fill ----------
__global__ void k_scan_part(const int* __restrict__ deg, int* __restrict__ bsum) {
    __shared__ int s[SCAN_B];
    int t = threadIdx.x, n = blockIdx.x * SCAN_B + t;
    s[t] = (n < NN) ? deg[n] : 0;
    __syncthreads();
    for (int d = SCAN_B / 2; d > 0; d >>= 1) {
        if (t < d) s[t] += s[t + d];
        __syncthreads();
    }
    if (t == 0) bsum[blockIdx.x] = s[0];
}

__global__ void k_scan_mid(const int* __restrict__ bsum, int* __restrict__ bpre) {
    __shared__ int s[128];
    int t = threadIdx.x;
    int v = (t < SCAN_NB) ? bsum[t] : 0;
    s[t] = v;
    __syncthreads();
    for (int d = 1; d < 128; d <<= 1) {
        int x = (t >= d) ? s[t - d] : 0;
        __syncthreads();
        s[t] += x;
        __syncthreads();
    }
    if (t < SCAN_NB) bpre[t] = s[t] - v;   // exclusive
}

__global__ void k_scan_add(const int* __restrict__ deg, const int* __restrict__ bpre,
                           int* __restrict__ off) {
    __shared__ int s[SCAN_B];
    int t = threadIdx.x, n = blockIdx.x * SCAN_B + t;
    int v = (n < NN) ? deg[n] : 0;
    s[t] = v;
    __syncthreads();
    for (int d = 1; d < SCAN_B; d <<= 1) {
        int x = (t >= d) ? s[t - d] : 0;
        __syncthreads();
        s[t] += x;
        __syncthreads();
    }
    if (n < NN) off[n] = bpre[blockIdx.x] + s[t] - v;   // exclusive
}

__global__ void k_fill(const int* __restrict__ src, const int* __restrict__ dst,
                       const int* __restrict__ off, int* __restrict__ cursor,
                       int* __restrict__ elist) {
    int e = blockIdx.x * blockDim.x + threadIdx.x;
    if (e >= NE) return;
    int d = dst[e];
    int p = atomicAdd(&cursor[d], 1);
    elist[off[d] + p] = src[e];
}

// ---------- mean aggregation: one warp per node, unroll 4 ----------
__global__ __launch_bounds__(256) void k_aggmean(
    const float* __restrict__ h, const int* __restrict__ elist,
    const int* __restrict__ off, const int* __restrict__ deg,
    float* __restrict__ mean) {
    int w = (blockIdx.x * blockDim.x + threadIdx.x) >> 5;
    int lane = threadIdx.x & 31;
    if (w >= NN) return;
    int beg = off[w], dg = deg[w];
    float2 a0 = make_float2(0.f, 0.f), a1 = a0, a2 = a0, a3 = a0;
    int i = beg, end = beg + dg;
    for (; i + 3 < end; i += 4) {
        int s0 = elist[i], s1 = elist[i + 1], s2 = elist[i + 2], s3 = elist[i + 3];
        float2 v0 = ((const float2*)(h + (size_t)s0 * DD))[lane];
        float2 v1 = ((const float2*)(h + (size_t)s1 * DD))[lane];
        float2 v2 = ((const float2*)(h + (size_t)s2 * DD))[lane];
        float2 v3 = ((const float2*)(h + (size_t)s3 * DD))[lane];
        a0.x += v0.x; a0.y += v0.y;
        a1.x += v1.x; a1.y += v1.y;
        a2.x += v2.x; a2.y += v2.y;
        a3.x += v3.x; a3.y += v3.y;
    }
    for (; i < end; ++i) {
        int s0 = elist[i];
        float2 v0 = ((const float2*)(h + (size_t)s0 * DD))[lane];
        a0.x += v0.x; a0.y += v0.y;
    }
    float inv = 1.0f / (float)max(dg, 1);
    float2 o = make_float2((a0.x + a1.x + a2.x + a3.x) * inv,
                           (a0.y + a1.y + a2.y + a3.y) * inv);
    ((float2*)(mean + (size_t)w * DD))[lane] = o;
}

// ---------- fused dual GEMM + bias + relu ----------
// out[n] = relu( mean[n] @ Wl^T + bl + h[n] @ Wr^T )
// Block: 128 threads, tile 128 nodes x 64 dims; thread: 8 nodes x 8 dims.
// sA stores A^T (k-major), node-blocks padded (b*8 + (b>>2)*4) -> stride 140.
#define SA_STRIDE 140
__device__ __forceinline__ int sa_blk(int b) { return b * 8 + (b >> 2) * 4; }

__global__ __launch_bounds__(128) void k_linear(
    const float* __restrict__ mean, const float* __restrict__ h,
    const float* __restrict__ Wl, const float* __restrict__ bl,
    const float* __restrict__ Wr, float* __restrict__ out)
{
    extern __shared__ float smem[];
    float* sW = smem;                 // [128][64]  (k-major, transposed)
    float* sA = smem + 128 * 64;      // [128][SA_STRIDE]
    const int tid = threadIdx.x;

    // Transposed weight staging, conflict-free STS (lanes vary in d).
    for (int i = tid; i < 2 * 64 * 64; i += 128) {
        int mat = i >> 12;
        int rem = i & 4095;
        int k = rem >> 6, d = rem & 63;
        float v = mat ? Wr[d * 64 + k] : Wl[d * 64 + k];
        sW[(mat * 64 + k) * 64 + d] = v;
    }

    const int nq = tid & 15;     // node group (8 nodes)
    const int dq = tid >> 4;     // dim group (8 dims)
    const int m0 = nq * 8;
    const int d0 = dq * 8;

    float4 bA = *(const float4*)&bl[d0];
    float4 bB = *(const float4*)&bl[d0 + 4];

    const int n0 = blockIdx.x * 128;
    const float4* m4 = (const float4*)mean;
    const float4* h4 = (const float4*)h;

    // Stage A^T: rows 0..63 = mean^T, 64..127 = h^T  (m == tid, coalesced STS)
    {
        int m = tid;   // 0..127
        int n = n0 + m;
        int col = sa_blk(m >> 3) + (m & 7);
        #pragma unroll
        for (int grp = 0; grp < 32; grp++) {
            int half = grp >> 4, kq = grp & 15;
            float4 v = make_float4(0.f, 0.f, 0.f, 0.f);
            if (n < NN) v = (half ? h4 : m4)[(size_t)n * 16 + kq];
            float* base = sA + (half * 64 + kq * 4) * SA_STRIDE + col;
            base[0 * SA_STRIDE] = v.x;
            base[1 * SA_STRIDE] = v.y;
            base[2 * SA_STRIDE] = v.z;
            base[3 * SA_STRIDE] = v.w;
        }
    }
    __syncthreads();

    // acc[node-pair p][dim j] : f32x2 over nodes (m0+2p, m0+2p+1)
    u64 acc[4][8];
    {
        u64 bb[8] = { pk2(bA.x, bA.x), pk2(bA.y, bA.y), pk2(bA.z, bA.z), pk2(bA.w, bA.w),
                      pk2(bB.x, bB.x), pk2(bB.y, bB.y), pk2(bB.z, bB.z), pk2(bB.w, bB.w) };
        #pragma unroll
        for (int p = 0; p < 4; p++)
            #pragma unroll
            for (int j = 0; j < 8; j++) acc[p][j] = bb[j];
    }

    const float* aptr = sA + sa_blk(nq);
    const float* wptr = sW + d0;

    #pragma unroll 4
    for (int k = 0; k < 128; k++) {
        float4 aA = *(const float4*)(aptr + k * SA_STRIDE);
        float4 aB = *(const float4*)(aptr + k * SA_STRIDE + 4);
        float4 wA = *(const float4*)(wptr + (size_t)k * 64);
        float4 wB = *(const float4*)(wptr + (size_t)k * 64 + 4);
        u64 pa0 = pk2(aA.x, aA.y), pa1 = pk2(aA.z, aA.w);
        u64 pa2 = pk2(aB.x, aB.y), pa3 = pk2(aB.z, aB.w);
        u64 wd0 = pk2(wA.x, wA.x), wd1 = pk2(wA.y, wA.y);
        u64 wd2 = pk2(wA.z, wA.z), wd3 = pk2(wA.w, wA.w);
        u64 wd4 = pk2(wB.x, wB.x), wd5 = pk2(wB.y, wB.y);
        u64 wd6 = pk2(wB.z, wB.z), wd7 = pk2(wB.w, wB.w);
        ffma2(acc[0][0], pa0, wd0); ffma2(acc[0][1], pa0, wd1);
        ffma2(acc[0][2], pa0, wd2); ffma2(acc[0][3], pa0, wd3);
        ffma2(acc[0][4], pa0, wd4); ffma2(acc[0][5], pa0, wd5);
        ffma2(acc[0][6], pa0, wd6); ffma2(acc[0][7], pa0, wd7);
        ffma2(acc[1][0], pa1, wd0); ffma2(acc[1][1], pa1, wd1);
        ffma2(acc[1][2], pa1, wd2); ffma2(acc[1][3], pa1, wd3);
        ffma2(acc[1][4], pa1, wd4); ffma2(acc[1][5], pa1, wd5);
        ffma2(acc[1][6], pa1, wd6); ffma2(acc[1][7], pa1, wd7);
        ffma2(acc[2][0], pa2, wd0); ffma2(acc[2][1], pa2, wd1);
        ffma2(acc[2][2], pa2, wd2); ffma2(acc[2][3], pa2, wd3);
        ffma2(acc[2][4], pa2, wd4); ffma2(acc[2][5], pa2, wd5);
        ffma2(acc[2][6], pa2, wd6); ffma2(acc[2][7], pa2, wd7);
        ffma2(acc[3][0], pa3, wd0); ffma2(acc[3][1], pa3, wd1);
        ffma2(acc[3][2], pa3, wd2); ffma2(acc[3][3], pa3, wd3);
        ffma2(acc[3][4], pa3, wd4); ffma2(acc[3][5], pa3, wd5);
        ffma2(acc[3][6], pa3, wd6); ffma2(acc[3][7], pa3, wd7);
    }

    #pragma unroll
    for (int p = 0; p < 4; p++) {
        float lo[8], hi[8];
        #pragma unroll
        for (int j = 0; j < 8; j++) upk2(lo[j], hi[j], acc[p][j]);
        int nA = n0 + m0 + 2 * p;
        int nB = nA + 1;
        if (nA < NN) {
            float4 oA = make_float4(fmaxf(lo[0], 0.f), fmaxf(lo[1], 0.f),
                                    fmaxf(lo[2], 0.f), fmaxf(lo[3], 0.f));
            float4 oB = make_float4(fmaxf(lo[4], 0.f), fmaxf(lo[5], 0.f),
                                    fmaxf(lo[6], 0.f), fmaxf(lo[7], 0.f));
            *(float4*)&out[(size_t)nA * DD + d0]     = oA;
            *(float4*)&out[(size_t)nA * DD + d0 + 4] = oB;
        }
        if (nB < NN) {
            float4 oA = make_float4(fmaxf(hi[0], 0.f), fmaxf(hi[1], 0.f),
                                    fmaxf(hi[2], 0.f), fmaxf(hi[3], 0.f));
            float4 oB = make_float4(fmaxf(hi[4], 0.f), fmaxf(hi[5], 0.f),
                                    fmaxf(hi[6], 0.f), fmaxf(hi[7], 0.f));
            *(float4*)&out[(size_t)nB * DD + d0]     = oA;
            *(float4*)&out[(size_t)nB * DD + d0 + 4] = oB;
        }
    }
}

// ---------- global mean pool ----------
__global__ void k_pool(const float* __restrict__ h, const int* __restrict__ batch,
                       float* __restrict__ pool, float* __restrict__ gcnt) {
    int t = blockIdx.x * blockDim.x + threadIdx.x;
    if (t >= NN * 4) return;
    int n = t >> 2, j = t & 3;
    int g = batch[n];
    const float4* hr = (const float4*)(h + (size_t)n * DD) + j * 4;
    float* p = pool + (size_t)g * DD + (size_t)j * 16;
    #pragma unroll
    for (int i = 0; i < 4; i++) red_v4(p + i * 4, hr[i]);
    if (j == 0) atomicAdd(&gcnt[g], 1.0f);
}

// ---------- classifier ----------
__global__ void k_out(const float* __restrict__ pool, const float* __restrict__ gcnt,
                      const float* __restrict__ Wout, const float* __restrict__ bout,
                      float* __restrict__ out) {
    int t = blockIdx.x * blockDim.x + threadIdx.x;
    if (t >= NG * 2) return;
    int g = t >> 1, c = t & 1;
    float inv = 1.0f / fmaxf(gcnt[g], 1.0f);
    float acc = bout[c];
    const float* p = pool + (size_t)g * DD;
    const float* w = Wout + (size_t)c * DD;
    #pragma unroll
    for (int k = 0; k < DD; k++) acc += p[k] * inv * w[k];
    out[(size_t)g * 2 + c] = acc;
}

extern "C" void kernel_launch(void* const* d_in, const int* in_sizes, int n_in,
                              void* d_out, int out_size) {
    const int*   x     = (const int*)d_in[0];
    const int*   ei    = (const int*)d_in[1];
    const int*   src   = ei;          // edge_index[0]
    const int*   dst   = ei + NE;     // edge_index[1]
    const int*   batch = (const int*)d_in[2];
    const float* emb   = (const float*)d_in[3];
    const float* W1l   = (const float*)d_in[4];
    const float* b1l   = (const float*)d_in[5];
    const float* W1r   = (const float*)d_in[6];
    const float* W2l   = (const float*)d_in[7];
    const float* b2l   = (const float*)d_in[8];
    const float* W2r   = (const float*)d_in[9];
    const float* Wout  = (const float*)d_in[10];
    const float* bout  = (const float*)d_in[11];
    float* out = (float*)d_out;

    float *h0, *h1, *h2, *mean, *pool, *gcnt;
    int *deg, *off, *cursor, *elist, *bsum, *bpre;
    cudaGetSymbolAddress((void**)&h0,     g_h0);
    cudaGetSymbolAddress((void**)&h1,     g_h1);
    cudaGetSymbolAddress((void**)&h2,     g_h2);
    cudaGetSymbolAddress((void**)&mean,   g_agg);
    cudaGetSymbolAddress((void**)&pool,   g_pool);
    cudaGetSymbolAddress((void**)&gcnt,   g_gcnt);
    cudaGetSymbolAddress((void**)&deg,    g_deg);
    cudaGetSymbolAddress((void**)&off,    g_off);
    cudaGetSymbolAddress((void**)&cursor, g_cursor);
    cudaGetSymbolAddress((void**)&elist,  g_elist);
    cudaGetSymbolAddress((void**)&bsum,   g_bsum);
    cudaGetSymbolAddress((void**)&bpre,   g_bpre);

    const int SMEM_LIN = (128 * 64 + 128 * SA_STRIDE) * 4;   // 104448 bytes
    cudaFuncSetAttribute(k_linear, cudaFuncAttributeMaxDynamicSharedMemorySize, SMEM_LIN);

    cudaMemsetAsync(deg,    0, NN * sizeof(int));
    cudaMemsetAsync(cursor, 0, NN * sizeof(int));
    cudaMemsetAsync(pool,   0, (size_t)NG * DD * sizeof(float));
    cudaMemsetAsync(gcnt,   0, NG * sizeof(float));

    const int T = 256;
    const int LIN_GRID = (NN + 127) / 128;   // 782

    // (1) embedding gather + degree count
    k_gatherdeg<<<(NN * 16 + NE + T - 1) / T, T>>>(x, emb, h0, dst, deg);
    // (2-4) scan for CSR offsets
    k_scan_part<<<SCAN_NB, SCAN_B>>>(deg, bsum);
    k_scan_mid<<<1, 128>>>(bsum, bpre);
    k_scan_add<<<SCAN_NB, SCAN_B>>>(deg, bpre, off);
    // (5) CSR fill
    k_fill<<<(NE + T - 1) / T, T>>>(src, dst, off, cursor, elist);

    // Layer 1   (aggmean is the 6th kernel launch -> gets profiled by ncu -s 5)
    k_aggmean<<<(NN * 32 + T - 1) / T, T>>>(h0, elist, off, deg, mean);
    k_linear<<<LIN_GRID, 128, SMEM_LIN>>>(mean, h0, W1l, b1l, W1r, h1);

    // Layer 2
    k_aggmean<<<(NN * 32 + T - 1) / T, T>>>(h1, elist, off, deg, mean);
    k_linear<<<LIN_GRID, 128, SMEM_LIN>>>(mean, h1, W2l, b2l, W2r, h2);

    // Pool + classify
    k_pool<<<(NN * 4 + T - 1) / T, T>>>(h2, batch, pool, gcnt);
    k_out<<<(NG * 2 + 127) / 128, 128>>>(pool, gcnt, Wout, bout, out);
}

// round 6
// speedup vs baseline: 1.1298x; 1.1298x over previous
#include <cuda_runtime.h>
#include <cuda_bf16.h>

#define NN 100000
#define NE 1200000
#define NG 2048
#define DD 64
#define SCAN_B 1024
#define SCAN_NB 98   // 98*1024 = 100352 >= NN

// Scratch (allocation-free, __device__ globals)
__device__ float g_h0[(size_t)NN * DD];
__device__ float g_h1[(size_t)NN * DD];
__device__ float g_h2[(size_t)NN * DD];
__device__ float g_agg[(size_t)NN * DD];      // mean buffer
__device__ float g_pool[(size_t)NG * DD];
__device__ float g_gcnt[NG];
__device__ int   g_deg[NN];
__device__ int   g_off[NN];
__device__ int   g_cursor[NN];
__device__ int   g_elist[NE];
__device__ int   g_bsum[SCAN_NB];
__device__ int   g_bpre[SCAN_NB];

typedef unsigned long long u64;

// ---------- packed fp32 helpers ----------
__device__ __forceinline__ u64 pk2(float lo, float hi) {
    u64 r;
    asm("mov.b64 %0, {%1, %2};" : "=l"(r) : "f"(lo), "f"(hi));
    return r;
}
__device__ __forceinline__ void upk2(float& lo, float& hi, u64 v) {
    asm("mov.b64 {%0, %1}, %2;" : "=f"(lo), "=f"(hi) : "l"(v));
}
__device__ __forceinline__ void ffma2(u64& acc, u64 a, u64 b) {
    asm("fma.rn.f32x2 %0, %1, %2, %0;" : "+l"(acc) : "l"(a), "l"(b));
}
__device__ __forceinline__ void red_v4(float* p, float4 v) {
    asm volatile("red.global.add.v4.f32 [%0], {%1, %2, %3, %4};"
                 :: "l"(p), "f"(v.x), "f"(v.y), "f"(v.z), "f"(v.w) : "memory");
}

// ---------- fused: h0[n] = emb[x[n]]  AND  deg[dst[e]] += 1 ----------
__global__ void k_gatherdeg(const int* __restrict__ x, const float* __restrict__ emb,
                            float* __restrict__ h, const int* __restrict__ dst,
                            int* __restrict__ deg) {
    int t = blockIdx.x * blockDim.x + threadIdx.x;
    if (t < NN * 16) {
        int n = t >> 4, j = t & 15;
        const float4* e = (const float4*)(emb + (size_t)x[n] * DD);
        ((float4*)(h + (size_t)n * DD))[j] = e[j];
    } else {
        int e = t - NN * 16;
        if (e < NE) atomicAdd(&deg[dst[e]], 1);
    }
}

// ---------- CSR build: scans + fill ----------
__global__ void k_scan_part(const int* __restrict__ deg, int* __restrict__ bsum) {
    __shared__ int s[SCAN_B];
    int t = threadIdx.x, n = blockIdx.x * SCAN_B + t;
    s[t] = (n < NN) ? deg[n] : 0;
    __syncthreads();
    for (int d = SCAN_B / 2; d > 0; d >>= 1) {
        if (t < d) s[t] += s[t + d];
        __syncthreads();
    }
    if (t == 0) bsum[blockIdx.x] = s[0];
}

__global__ void k_scan_mid(const int* __restrict__ bsum, int* __restrict__ bpre) {
    __shared__ int s[128];
    int t = threadIdx.x;
    int v = (t < SCAN_NB) ? bsum[t] : 0;
    s[t] = v;
    __syncthreads();
    for (int d = 1; d < 128; d <<= 1) {
        int x = (t >= d) ? s[t - d] : 0;
        __syncthreads();
        s[t] += x;
        __syncthreads();
    }
    if (t < SCAN_NB) bpre[t] = s[t] - v;   // exclusive
}

__global__ void k_scan_add(const int* __restrict__ deg, const int* __restrict__ bpre,
                           int* __restrict__ off) {
    __shared__ int s[SCAN_B];
    int t = threadIdx.x, n = blockIdx.x * SCAN_B + t;
    int v = (n < NN) ? deg[n] : 0;
    s[t] = v;
    __syncthreads();
    for (int d = 1; d < SCAN_B; d <<= 1) {
        int x = (t >= d) ? s[t - d] : 0;
        __syncthreads();
        s[t] += x;
        __syncthreads();
    }
    if (n < NN) off[n] = bpre[blockIdx.x] + s[t] - v;   // exclusive
}

__global__ void k_fill(const int* __restrict__ src, const int* __restrict__ dst,
                       const int* __restrict__ off, int* __restrict__ cursor,
                       int* __restrict__ elist) {
    int e = blockIdx.x * blockDim.x + threadIdx.x;
    if (e >= NE) return;
    int d = dst[e];
    int p = atomicAdd(&cursor[d], 1);
    elist[off[d] + p] = src[e];
}

// ---------- mean aggregation: one warp per node, unroll 4 ----------
__global__ __launch_bounds__(256) void k_aggmean(
    const float* __restrict__ h, const int* __restrict__ elist,
    const int* __restrict__ off, const int* __restrict__ deg,
    float* __restrict__ mean) {
    int w = (blockIdx.x * blockDim.x + threadIdx.x) >> 5;
    int lane = threadIdx.x & 31;
    if (w >= NN) return;
    int beg = off[w], dg = deg[w];
    float2 a0 = make_float2(0.f, 0.f), a1 = a0, a2 = a0, a3 = a0;
    int i = beg, end = beg + dg;
    for (; i + 3 < end; i += 4) {
        int s0 = elist[i], s1 = elist[i + 1], s2 = elist[i + 2], s3 = elist[i + 3];
        float2 v0 = ((const float2*)(h + (size_t)s0 * DD))[lane];
        float2 v1 = ((const float2*)(h + (size_t)s1 * DD))[lane];
        float2 v2 = ((const float2*)(h + (size_t)s2 * DD))[lane];
        float2 v3 = ((const float2*)(h + (size_t)s3 * DD))[lane];
        a0.x += v0.x; a0.y += v0.y;
        a1.x += v1.x; a1.y += v1.y;
        a2.x += v2.x; a2.y += v2.y;
        a3.x += v3.x; a3.y += v3.y;
    }
    for (; i < end; ++i) {
        int s0 = elist[i];
        float2 v0 = ((const float2*)(h + (size_t)s0 * DD))[lane];
        a0.x += v0.x; a0.y += v0.y;
    }
    float inv = 1.0f / (float)max(dg, 1);
    float2 o = make_float2((a0.x + a1.x + a2.x + a3.x) * inv,
                           (a0.y + a1.y + a2.y + a3.y) * inv);
    ((float2*)(mean + (size_t)w * DD))[lane] = o;
}

// ---------- fused dual GEMM + bias + relu (R4 version — measured best) ----------
// out[n] = relu( mean[n] @ Wl^T + bl + h[n] @ Wr^T )
// 64 nodes x 64 dims per block, 256 threads, 4x4 micro-tile, FFMA2 (fma.rn.f32x2).
#define SA_STRIDE 68
__global__ __launch_bounds__(256) void k_linear(
    const float* __restrict__ mean, const float* __restrict__ h,
    const float* __restrict__ Wl, const float* __restrict__ bl,
    const float* __restrict__ Wr, float* __restrict__ out)
{
    extern __shared__ float smem[];
    float* sW = smem;                 // [128][64]
    float* sA = smem + 128 * 64;      // [128][SA_STRIDE] swizzled
    const int tid = threadIdx.x;

    // Weights transposed: sW[k][d] = Wl[d][k]; sW[64+k][d] = Wr[d][k]
    for (int i = tid; i < 64 * 64; i += 256) {
        int d = i >> 6, k = i & 63;
        sW[k * 64 + d]        = Wl[i];
        sW[(64 + k) * 64 + d] = Wr[i];
    }

    const int q  = tid & 15;     // node quad
    const int dq = tid >> 4;     // dim quad
    const int d0 = dq * 4;
    float4 bias = *(const float4*)&bl[d0];
    __syncthreads();

    const float4* m4 = (const float4*)mean;
    const float4* h4 = (const float4*)h;

    for (int n0 = blockIdx.x * 64; n0 < NN; n0 += gridDim.x * 64) {
        // Stage A^T swizzled: rows 0..63 = mean^T, 64..127 = h^T
        for (int i = tid; i < 64 * 16; i += 256) {
            int m = i >> 4, kq = i & 15;
            int n = n0 + m;
            float4 va = make_float4(0.f, 0.f, 0.f, 0.f), vh = va;
            if (n < NN) {
                va = m4[(size_t)n * 16 + kq];
                vh = h4[(size_t)n * 16 + kq];
            }
            int mb = m >> 2, mw = m & 3;
            int col = ((mb + kq) & 15) * 4 + mw;
            int k = kq * 4;
            sA[(k + 0) * SA_STRIDE + col] = va.x;
            sA[(k + 1) * SA_STRIDE + col] = va.y;
            sA[(k + 2) * SA_STRIDE + col] = va.z;
            sA[(k + 3) * SA_STRIDE + col] = va.w;
            sA[(64 + k + 0) * SA_STRIDE + col] = vh.x;
            sA[(64 + k + 1) * SA_STRIDE + col] = vh.y;
            sA[(64 + k + 2) * SA_STRIDE + col] = vh.z;
            sA[(64 + k + 3) * SA_STRIDE + col] = vh.w;
        }
        __syncthreads();

        // acc[node i][dim-pair j] : f32x2 over dims (d0+2j, d0+2j+1)
        u64 acc[4][2];
        u64 b01 = pk2(bias.x, bias.y);
        u64 b23 = pk2(bias.z, bias.w);
        #pragma unroll
        for (int i = 0; i < 4; i++) { acc[i][0] = b01; acc[i][1] = b23; }

        #pragma unroll
        for (int kq = 0; kq < 32; kq++) {
            int col = ((q + kq) & 15) * 4;
            const float* ar = &sA[(kq * 4) * SA_STRIDE + col];
            #pragma unroll
            for (int c = 0; c < 4; c++) {
                int k = kq * 4 + c;
                float4 a = *(const float4*)(ar + c * SA_STRIDE);
                float4 w = *(const float4*)&sW[k * 64 + d0];
                u64 w01 = pk2(w.x, w.y);
                u64 w23 = pk2(w.z, w.w);
                u64 ax = pk2(a.x, a.x);
                u64 ay = pk2(a.y, a.y);
                u64 az = pk2(a.z, a.z);
                u64 aw = pk2(a.w, a.w);
                ffma2(acc[0][0], ax, w01); ffma2(acc[0][1], ax, w23);
                ffma2(acc[1][0], ay, w01); ffma2(acc[1][1], ay, w23);
                ffma2(acc[2][0], az, w01); ffma2(acc[2][1], az, w23);
                ffma2(acc[3][0], aw, w01); ffma2(acc[3][1], aw, w23);
            }
        }

        int m0 = q * 4;
        #pragma unroll
        for (int i = 0; i < 4; i++) {
            int n = n0 + m0 + i;
            if (n < NN) {
                float o0, o1, o2, o3;
                upk2(o0, o1, acc[i][0]);
                upk2(o2, o3, acc[i][1]);
                float4 o = make_float4(fmaxf(o0, 0.f), fmaxf(o1, 0.f),
                                       fmaxf(o2, 0.f), fmaxf(o3, 0.f));
                *(float4*)&out[(size_t)n * DD + d0] = o;
            }
        }
        __syncthreads();
    }
}

// ---------- global mean pool ----------
__global__ void k_pool(const float* __restrict__ h, const int* __restrict__ batch,
                       float* __restrict__ pool, float* __restrict__ gcnt) {
    int t = blockIdx.x * blockDim.x + threadIdx.x;
    if (t >= NN * 4) return;
    int n = t >> 2, j = t & 3;
    int g = batch[n];
    const float4* hr = (const float4*)(h + (size_t)n * DD) + j * 4;
    float* p = pool + (size_t)g * DD + (size_t)j * 16;
    #pragma unroll
    for (int i = 0; i < 4; i++) red_v4(p + i * 4, hr[i]);
    if (j == 0) atomicAdd(&gcnt[g], 1.0f);
}

// ---------- classifier ----------
__global__ void k_out(const float* __restrict__ pool, const float* __restrict__ gcnt,
                      const float* __restrict__ Wout, const float* __restrict__ bout,
                      float* __restrict__ out) {
    int t = blockIdx.x * blockDim.x + threadIdx.x;
    if (t >= NG * 2) return;
    int g = t >> 1, c = t & 1;
    float inv = 1.0f / fmaxf(gcnt[g], 1.0f);
    float acc = bout[c];
    const float* p = pool + (size_t)g * DD;
    const float* w = Wout + (size_t)c * DD;
    #pragma unroll
    for (int k = 0; k < DD; k++) acc += p[k] * inv * w[k];
    out[(size_t)g * 2 + c] = acc;
}

extern "C" void kernel_launch(void* const* d_in, const int* in_sizes, int n_in,
                              void* d_out, int out_size) {
    const int*   x     = (const int*)d_in[0];
    const int*   ei    = (const int*)d_in[1];
    const int*   src   = ei;          // edge_index[0]
    const int*   dst   = ei + NE;     // edge_index[1]
    const int*   batch = (const int*)d_in[2];
    const float* emb   = (const float*)d_in[3];
    const float* W1l   = (const float*)d_in[4];
    const float* b1l   = (const float*)d_in[5];
    const float* W1r   = (const float*)d_in[6];
    const float* W2l   = (const float*)d_in[7];
    const float* b2l   = (const float*)d_in[8];
    const float* W2r   = (const float*)d_in[9];
    const float* Wout  = (const float*)d_in[10];
    const float* bout  = (const float*)d_in[11];
    float* out = (float*)d_out;

    float *h0, *h1, *h2, *mean, *pool, *gcnt;
    int *deg, *off, *cursor, *elist, *bsum, *bpre;
    cudaGetSymbolAddress((void**)&h0,     g_h0);
    cudaGetSymbolAddress((void**)&h1,     g_h1);
    cudaGetSymbolAddress((void**)&h2,     g_h2);
    cudaGetSymbolAddress((void**)&mean,   g_agg);
    cudaGetSymbolAddress((void**)&pool,   g_pool);
    cudaGetSymbolAddress((void**)&gcnt,   g_gcnt);
    cudaGetSymbolAddress((void**)&deg,    g_deg);
    cudaGetSymbolAddress((void**)&off,    g_off);
    cudaGetSymbolAddress((void**)&cursor, g_cursor);
    cudaGetSymbolAddress((void**)&elist,  g_elist);
    cudaGetSymbolAddress((void**)&bsum,   g_bsum);
    cudaGetSymbolAddress((void**)&bpre,   g_bpre);

    const int SMEM_LIN = (128 * 64 + 128 * SA_STRIDE) * 4;   // 67584 bytes
    cudaFuncSetAttribute(k_linear, cudaFuncAttributeMaxDynamicSharedMemorySize, SMEM_LIN);

    cudaMemsetAsync(deg,    0, NN * sizeof(int));
    cudaMemsetAsync(cursor, 0, NN * sizeof(int));
    cudaMemsetAsync(pool,   0, (size_t)NG * DD * sizeof(float));
    cudaMemsetAsync(gcnt,   0, NG * sizeof(float));

    const int T = 256;

    // (1) embedding gather + degree count
    k_gatherdeg<<<(NN * 16 + NE + T - 1) / T, T>>>(x, emb, h0, dst, deg);
    // (2-4) scan for CSR offsets
    k_scan_part<<<SCAN_NB, SCAN_B>>>(deg, bsum);
    k_scan_mid<<<1, 128>>>(bsum, bpre);
    k_scan_add<<<SCAN_NB, SCAN_B>>>(deg, bpre, off);
    // (5) CSR fill
    k_fill<<<(NE + T - 1) / T, T>>>(src, dst, off, cursor, elist);

    // Layer 1   (aggmean is the 6th kernel launch -> profiled by ncu -s 5)
    k_aggmean<<<(NN * 32 + T - 1) / T, T>>>(h0, elist, off, deg, mean);
    k_linear<<<444, 256, SMEM_LIN>>>(mean, h0, W1l, b1l, W1r, h1);

    // Layer 2
    k_aggmean<<<(NN * 32 + T - 1) / T, T>>>(h1, elist, off, deg, mean);
    k_linear<<<444, 256, SMEM_LIN>>>(mean, h1, W2l, b2l, W2r, h2);

    // Pool + classify
    k_pool<<<(NN * 4 + T - 1) / T, T>>>(h2, batch, pool, gcnt);
    k_out<<<(NG * 2 + 127) / 128, 128>>>(pool, gcnt, Wout, bout, out);
}